// round 2
// baseline (speedup 1.0000x reference)
#include <cuda_runtime.h>
#include <cstdint>

#define BL   (4 * 4096)   // B*L tokens
#define DIM  1024
#define HEADS 16
#define HD    64

// Scratch for Q, K, V projections (192 MB static device memory — allowed).
__device__ float g_qkv[3][(size_t)BL * DIM];

__device__ __forceinline__ uint32_t f2tf32(float x) {
    uint32_t y;
    asm("cvt.rna.tf32.f32 %0, %1;" : "=r"(y) : "f"(x));
    return y;
}

__device__ __forceinline__ void mma_tf32(float* d,
    uint32_t a0, uint32_t a1, uint32_t a2, uint32_t a3,
    uint32_t b0, uint32_t b1)
{
    asm volatile(
        "mma.sync.aligned.m16n8k8.row.col.f32.tf32.tf32.f32 "
        "{%0,%1,%2,%3}, {%4,%5,%6,%7}, {%8,%9}, {%0,%1,%2,%3};"
        : "+f"(d[0]), "+f"(d[1]), "+f"(d[2]), "+f"(d[3])
        : "r"(a0), "r"(a1), "r"(a2), "r"(a3), "r"(b0), "r"(b1));
}

// C[m][n] = sum_k X[m][k] * W[n][k]   (torch Linear: x @ W.T)
// Tile: 128x128x32, 8 warps (2 in M x 4 in N), warp tile 64x32 via m16n8k8 tf32.
__global__ __launch_bounds__(256) void qkv_gemm(
    const float* __restrict__ X,
    const float* __restrict__ Wq,
    const float* __restrict__ Wk,
    const float* __restrict__ Wv)
{
    const int z = blockIdx.z;
    const float* W = (z == 0) ? Wq : (z == 1) ? Wk : Wv;
    float* C = g_qkv[z];

    const int bm = blockIdx.y * 128;
    const int bn = blockIdx.x * 128;

    // ld = 36 makes the mma fragment gather conflict-free: bank(36*r + c) = 4r + c
    __shared__ __align__(16) uint32_t As[128][36];
    __shared__ __align__(16) uint32_t Bs[128][36];

    const int tid  = threadIdx.x;
    const int warp = tid >> 5;
    const int lane = tid & 31;
    const int wm = (warp & 1) * 64;
    const int wn = (warp >> 1) * 32;
    const int g  = lane >> 2;   // groupID
    const int t  = lane & 3;    // threadID_in_group

    float acc[4][4][4];
    #pragma unroll
    for (int i = 0; i < 4; i++)
        #pragma unroll
        for (int j = 0; j < 4; j++)
            #pragma unroll
            for (int k = 0; k < 4; k++) acc[i][j][k] = 0.f;

    for (int k0 = 0; k0 < DIM; k0 += 32) {
        // Cooperative tile load: 128x32 fp32 each for A and B, tf32-rounded.
        #pragma unroll
        for (int i = 0; i < 4; i++) {
            int idx = tid + i * 256;       // 0..1023
            int r = idx >> 3;
            int c = (idx & 7) * 4;
            float4 va = *(const float4*)(X + (size_t)(bm + r) * DIM + k0 + c);
            uint32_t* pa = &As[r][c];
            pa[0] = f2tf32(va.x); pa[1] = f2tf32(va.y);
            pa[2] = f2tf32(va.z); pa[3] = f2tf32(va.w);
            float4 vb = *(const float4*)(W + (size_t)(bn + r) * DIM + k0 + c);
            uint32_t* pb = &Bs[r][c];
            pb[0] = f2tf32(vb.x); pb[1] = f2tf32(vb.y);
            pb[2] = f2tf32(vb.z); pb[3] = f2tf32(vb.w);
        }
        __syncthreads();

        #pragma unroll
        for (int ks = 0; ks < 4; ks++) {
            const int kb = ks * 8;
            uint32_t a[4][4], b[4][2];
            #pragma unroll
            for (int mt = 0; mt < 4; mt++) {
                const int row = wm + mt * 16;
                a[mt][0] = As[row + g    ][kb + t];
                a[mt][1] = As[row + g + 8][kb + t];
                a[mt][2] = As[row + g    ][kb + t + 4];
                a[mt][3] = As[row + g + 8][kb + t + 4];
            }
            #pragma unroll
            for (int nt = 0; nt < 4; nt++) {
                const int col = wn + nt * 8;
                b[nt][0] = Bs[col + g][kb + t];
                b[nt][1] = Bs[col + g][kb + t + 4];
            }
            #pragma unroll
            for (int mt = 0; mt < 4; mt++)
                #pragma unroll
                for (int nt = 0; nt < 4; nt++)
                    mma_tf32(acc[mt][nt],
                             a[mt][0], a[mt][1], a[mt][2], a[mt][3],
                             b[nt][0], b[nt][1]);
        }
        __syncthreads();
    }

    #pragma unroll
    for (int mt = 0; mt < 4; mt++) {
        #pragma unroll
        for (int nt = 0; nt < 4; nt++) {
            int row = bm + wm + mt * 16 + g;
            int col = bn + wn + nt * 8 + t * 2;
            *(float2*)&C[(size_t)row * DIM + col] =
                make_float2(acc[mt][nt][0], acc[mt][nt][1]);
            *(float2*)&C[(size_t)(row + 8) * DIM + col] =
                make_float2(acc[mt][nt][2], acc[mt][nt][3]);
        }
    }
}

// One block per token. out = (softmax_hd(Q) @ softmax_heads(K^T)) @ V
// Associativity rewrite: 16x16 intermediate instead of 64x64 (-50% FLOPs).
__global__ __launch_bounds__(128) void attn(float* __restrict__ out)
{
    const int tok = blockIdx.x;
    const int tid = threadIdx.x;

    __shared__ __align__(16) float sQ[HEADS][68];   // padded: conflict-free M-stage reads
    __shared__ __align__(16) float sK[HD][17];      // sK[d][h]
    __shared__ __align__(16) float sV[HEADS][HD];
    __shared__ __align__(16) float sM[HEADS][17];

    const float* Qp = g_qkv[0] + (size_t)tok * DIM;
    const float* Kp = g_qkv[1] + (size_t)tok * DIM;
    const float* Vp = g_qkv[2] + (size_t)tok * DIM;

    // Load Q, V directly; K transposed into sK[d][h].
    #pragma unroll
    for (int i = tid; i < 256; i += 128) {
        int h = i >> 4;            // (i*4)/64
        int d = (i & 15) * 4;      // (i*4)%64
        float4 q = ((const float4*)Qp)[i];
        *(float4*)&sQ[h][d] = q;
        float4 v = ((const float4*)Vp)[i];
        *(float4*)&sV[h][d] = v;
        float4 kf = ((const float4*)Kp)[i];
        sK[d + 0][h] = kf.x; sK[d + 1][h] = kf.y;
        sK[d + 2][h] = kf.z; sK[d + 3][h] = kf.w;
    }
    __syncthreads();

    if (tid < 64) {
        // softmax over heads for each dim d (on K^T)
        const int d = tid;
        float mx = -1e30f;
        #pragma unroll
        for (int h = 0; h < HEADS; h++) mx = fmaxf(mx, sK[d][h]);
        float e[HEADS], s = 0.f;
        #pragma unroll
        for (int h = 0; h < HEADS; h++) { e[h] = __expf(sK[d][h] - mx); s += e[h]; }
        const float r = 1.f / s;
        #pragma unroll
        for (int h = 0; h < HEADS; h++) sK[d][h] = e[h] * r;
    } else if (tid < 64 + HEADS) {
        // softmax over head_dim for each head h (on Q)
        const int h = tid - 64;
        float mx = -1e30f;
        for (int d = 0; d < HD; d++) mx = fmaxf(mx, sQ[h][d]);
        float s = 0.f;
        for (int d = 0; d < HD; d++) { float e = __expf(sQ[h][d] - mx); sQ[h][d] = e; s += e; }
        const float r = 1.f / s;
        for (int d = 0; d < HD; d++) sQ[h][d] *= r;
    }
    __syncthreads();

    // M(16x16) = sQ(16x64) @ sK(64x16): 64 threads, 2x2 register tiles.
    if (tid < 64) {
        const int i0 = (tid >> 3) * 2;
        const int j0 = (tid & 7) * 2;
        float m00 = 0.f, m01 = 0.f, m10 = 0.f, m11 = 0.f;
        #pragma unroll 8
        for (int d = 0; d < HD; d++) {
            float q0 = sQ[i0][d],     q1 = sQ[i0 + 1][d];
            float k0 = sK[d][j0],     k1 = sK[d][j0 + 1];
            m00 += q0 * k0; m01 += q0 * k1;
            m10 += q1 * k0; m11 += q1 * k1;
        }
        sM[i0][j0]     = m00; sM[i0][j0 + 1]     = m01;
        sM[i0 + 1][j0] = m10; sM[i0 + 1][j0 + 1] = m11;
    }
    __syncthreads();

    // out(16x64) = M(16x16) @ V(16x64): thread -> (h, 8 consecutive e)
    const int h  = tid >> 3;
    const int e0 = (tid & 7) * 8;
    float o[8];
    #pragma unroll
    for (int i = 0; i < 8; i++) o[i] = 0.f;
    #pragma unroll
    for (int k = 0; k < HEADS; k++) {
        const float m = sM[h][k];
        const float4 v0 = *(const float4*)&sV[k][e0];
        const float4 v1 = *(const float4*)&sV[k][e0 + 4];
        o[0] += m * v0.x; o[1] += m * v0.y; o[2] += m * v0.z; o[3] += m * v0.w;
        o[4] += m * v1.x; o[5] += m * v1.y; o[6] += m * v1.z; o[7] += m * v1.w;
    }
    float* O = out + (size_t)tok * DIM + tid * 8;  // h*64 + e0 == tid*8
    *(float4*)O       = make_float4(o[0], o[1], o[2], o[3]);
    *(float4*)(O + 4) = make_float4(o[4], o[5], o[6], o[7]);
}

extern "C" void kernel_launch(void* const* d_in, const int* in_sizes, int n_in,
                              void* d_out, int out_size)
{
    const float* X  = (const float*)d_in[0];
    const float* Wq = (const float*)d_in[1];
    const float* Wk = (const float*)d_in[2];
    const float* Wv = (const float*)d_in[3];
    float* out = (float*)d_out;

    dim3 grid_gemm(DIM / 128, BL / 128, 3);   // (8, 128, 3)
    qkv_gemm<<<grid_gemm, 256>>>(X, Wq, Wk, Wv);
    attn<<<BL, 128>>>(out);
}

// round 4
// speedup vs baseline: 1.1558x; 1.1558x over previous
#include <cuda_runtime.h>
#include <cstdint>

#define BL   (4 * 4096)   // B*L tokens
#define DIM  1024
#define HEADS 16
#define HD    64

// Scratch for Q, K, V projections (192 MB static device memory — allowed).
__device__ float g_qkv[3][(size_t)BL * DIM];

__device__ __forceinline__ uint32_t f2tf32(float x) {
    uint32_t y;
    asm("cvt.rna.tf32.f32 %0, %1;" : "=r"(y) : "f"(x));
    return y;
}

__device__ __forceinline__ void mma_tf32(float* d,
    uint32_t a0, uint32_t a1, uint32_t a2, uint32_t a3,
    uint32_t b0, uint32_t b1)
{
    asm volatile(
        "mma.sync.aligned.m16n8k8.row.col.f32.tf32.tf32.f32 "
        "{%0,%1,%2,%3}, {%4,%5,%6,%7}, {%8,%9}, {%0,%1,%2,%3};"
        : "+f"(d[0]), "+f"(d[1]), "+f"(d[2]), "+f"(d[3])
        : "r"(a0), "r"(a1), "r"(a2), "r"(a3), "r"(b0), "r"(b1));
}

__device__ __forceinline__ void cp16(float* smem_dst, const float* gsrc) {
    uint32_t s = (uint32_t)__cvta_generic_to_shared(smem_dst);
    asm volatile("cp.async.cg.shared.global [%0], [%1], 16;" :: "r"(s), "l"(gsrc));
}

// SMEM tile geometry: [128 rows][36 floats] per stage (pad 36 => conflict-free
// fragment gather: bank(36*g + t) = 4g + t covers all 32 banks).
#define LDK 36
#define STAGE_ELEMS (128 * LDK)

// C[m][n] = sum_k X[m][k] * W[n][k]   (torch Linear: x @ W.T)
// Tile: 128x128x32, 8 warps (2M x 4N), warp 64x32 via m16n8k8 tf32.
// cp.async double-buffered mainloop; fp32 in SMEM, cvt->tf32 at fragment load.
__global__ __launch_bounds__(256, 2) void qkv_gemm(
    const float* __restrict__ X,
    const float* __restrict__ Wq,
    const float* __restrict__ Wk,
    const float* __restrict__ Wv)
{
    extern __shared__ float smem[];
    float* As = smem;                       // [2][128][LDK]
    float* Bs = smem + 2 * STAGE_ELEMS;     // [2][128][LDK]

    const int z = blockIdx.z;
    const float* W = (z == 0) ? Wq : (z == 1) ? Wk : Wv;
    float* C = g_qkv[z];

    const int bm = blockIdx.y * 128;
    const int bn = blockIdx.x * 128;

    const int tid  = threadIdx.x;
    const int warp = tid >> 5;
    const int lane = tid & 31;
    const int wm = (warp & 1) * 64;
    const int wn = (warp >> 1) * 32;
    const int g  = lane >> 2;   // groupID
    const int t  = lane & 3;    // threadID_in_group

    // Per-thread cooperative-load coordinates (4 float4 per array per stage).
    int ldr[4], ldc[4];
    #pragma unroll
    for (int i = 0; i < 4; i++) {
        int idx = tid + i * 256;    // 0..1023
        ldr[i] = idx >> 3;
        ldc[i] = (idx & 7) * 4;
    }

    float acc[4][4][4];
    #pragma unroll
    for (int i = 0; i < 4; i++)
        #pragma unroll
        for (int j = 0; j < 4; j++)
            #pragma unroll
            for (int k = 0; k < 4; k++) acc[i][j][k] = 0.f;

    const int NTILE = DIM / 32;

    // ---- prologue: issue tile 0 into stage 0 ----
    #pragma unroll
    for (int i = 0; i < 4; i++) {
        cp16(As + ldr[i] * LDK + ldc[i], X + (size_t)(bm + ldr[i]) * DIM + ldc[i]);
        cp16(Bs + ldr[i] * LDK + ldc[i], W + (size_t)(bn + ldr[i]) * DIM + ldc[i]);
    }
    asm volatile("cp.async.commit_group;");

    for (int kt = 0; kt < NTILE; kt++) {
        // Issue next tile into the other stage, then wait for current tile.
        if (kt + 1 < NTILE) {
            const int k0 = (kt + 1) * 32;
            float* Ad = As + ((kt + 1) & 1) * STAGE_ELEMS;
            float* Bd = Bs + ((kt + 1) & 1) * STAGE_ELEMS;
            #pragma unroll
            for (int i = 0; i < 4; i++) {
                cp16(Ad + ldr[i] * LDK + ldc[i],
                     X + (size_t)(bm + ldr[i]) * DIM + k0 + ldc[i]);
                cp16(Bd + ldr[i] * LDK + ldc[i],
                     W + (size_t)(bn + ldr[i]) * DIM + k0 + ldc[i]);
            }
            asm volatile("cp.async.commit_group;");
            asm volatile("cp.async.wait_group 1;");
        } else {
            asm volatile("cp.async.wait_group 0;");
        }
        __syncthreads();

        const float* Ac = As + (kt & 1) * STAGE_ELEMS;
        const float* Bc = Bs + (kt & 1) * STAGE_ELEMS;

        #pragma unroll
        for (int ks = 0; ks < 4; ks++) {
            const int kb = ks * 8;
            uint32_t a[4][4], b[4][2];
            #pragma unroll
            for (int mt = 0; mt < 4; mt++) {
                const int row = wm + mt * 16;
                a[mt][0] = f2tf32(Ac[(row + g    ) * LDK + kb + t]);
                a[mt][1] = f2tf32(Ac[(row + g + 8) * LDK + kb + t]);
                a[mt][2] = f2tf32(Ac[(row + g    ) * LDK + kb + t + 4]);
                a[mt][3] = f2tf32(Ac[(row + g + 8) * LDK + kb + t + 4]);
            }
            #pragma unroll
            for (int nt = 0; nt < 4; nt++) {
                const int col = wn + nt * 8;
                b[nt][0] = f2tf32(Bc[(col + g) * LDK + kb + t]);
                b[nt][1] = f2tf32(Bc[(col + g) * LDK + kb + t + 4]);
            }
            #pragma unroll
            for (int mt = 0; mt < 4; mt++)
                #pragma unroll
                for (int nt = 0; nt < 4; nt++)
                    mma_tf32(acc[mt][nt],
                             a[mt][0], a[mt][1], a[mt][2], a[mt][3],
                             b[nt][0], b[nt][1]);
        }
        __syncthreads();   // stage (kt&1) may be overwritten at iter kt+1
    }

    #pragma unroll
    for (int mt = 0; mt < 4; mt++) {
        #pragma unroll
        for (int nt = 0; nt < 4; nt++) {
            int row = bm + wm + mt * 16 + g;
            int col = bn + wn + nt * 8 + t * 2;
            *(float2*)&C[(size_t)row * DIM + col] =
                make_float2(acc[mt][nt][0], acc[mt][nt][1]);
            *(float2*)&C[(size_t)(row + 8) * DIM + col] =
                make_float2(acc[mt][nt][2], acc[mt][nt][3]);
        }
    }
}

// One block per token. out = (softmax_hd(Q) @ softmax_heads(K^T)) @ V
// Associativity rewrite: 16x16 intermediate instead of 64x64 (-50% FLOPs).
__global__ __launch_bounds__(128) void attn(float* __restrict__ out)
{
    const int tok = blockIdx.x;
    const int tid = threadIdx.x;

    __shared__ __align__(16) float sQ[HEADS][68];
    __shared__ __align__(16) float sK[HD][17];
    __shared__ __align__(16) float sV[HEADS][HD];
    __shared__ __align__(16) float sM[HEADS][17];

    const float* Qp = g_qkv[0] + (size_t)tok * DIM;
    const float* Kp = g_qkv[1] + (size_t)tok * DIM;
    const float* Vp = g_qkv[2] + (size_t)tok * DIM;

    #pragma unroll
    for (int i = tid; i < 256; i += 128) {
        int h = i >> 4;
        int d = (i & 15) * 4;
        float4 q = ((const float4*)Qp)[i];
        *(float4*)&sQ[h][d] = q;
        float4 v = ((const float4*)Vp)[i];
        *(float4*)&sV[h][d] = v;
        float4 kf = ((const float4*)Kp)[i];
        sK[d + 0][h] = kf.x; sK[d + 1][h] = kf.y;
        sK[d + 2][h] = kf.z; sK[d + 3][h] = kf.w;
    }
    __syncthreads();

    if (tid < 64) {
        const int d = tid;
        float mx = -1e30f;
        #pragma unroll
        for (int h = 0; h < HEADS; h++) mx = fmaxf(mx, sK[d][h]);
        float e[HEADS], s = 0.f;
        #pragma unroll
        for (int h = 0; h < HEADS; h++) { e[h] = __expf(sK[d][h] - mx); s += e[h]; }
        const float r = 1.f / s;
        #pragma unroll
        for (int h = 0; h < HEADS; h++) sK[d][h] = e[h] * r;
    } else if (tid < 64 + HEADS) {
        const int h = tid - 64;
        float mx = -1e30f;
        for (int d = 0; d < HD; d++) mx = fmaxf(mx, sQ[h][d]);
        float s = 0.f;
        for (int d = 0; d < HD; d++) { float e = __expf(sQ[h][d] - mx); sQ[h][d] = e; s += e; }
        const float r = 1.f / s;
        for (int d = 0; d < HD; d++) sQ[h][d] *= r;
    }
    __syncthreads();

    if (tid < 64) {
        const int i0 = (tid >> 3) * 2;
        const int j0 = (tid & 7) * 2;
        float m00 = 0.f, m01 = 0.f, m10 = 0.f, m11 = 0.f;
        #pragma unroll 8
        for (int d = 0; d < HD; d++) {
            float q0 = sQ[i0][d],     q1 = sQ[i0 + 1][d];
            float k0 = sK[d][j0],     k1 = sK[d][j0 + 1];
            m00 += q0 * k0; m01 += q0 * k1;
            m10 += q1 * k0; m11 += q1 * k1;
        }
        sM[i0][j0]     = m00; sM[i0][j0 + 1]     = m01;
        sM[i0 + 1][j0] = m10; sM[i0 + 1][j0 + 1] = m11;
    }
    __syncthreads();

    const int h  = tid >> 3;
    const int e0 = (tid & 7) * 8;
    float o[8];
    #pragma unroll
    for (int i = 0; i < 8; i++) o[i] = 0.f;
    #pragma unroll
    for (int k = 0; k < HEADS; k++) {
        const float m = sM[h][k];
        const float4 v0 = *(const float4*)&sV[k][e0];
        const float4 v1 = *(const float4*)&sV[k][e0 + 4];
        o[0] += m * v0.x; o[1] += m * v0.y; o[2] += m * v0.z; o[3] += m * v0.w;
        o[4] += m * v1.x; o[5] += m * v1.y; o[6] += m * v1.z; o[7] += m * v1.w;
    }
    float* O = out + (size_t)tok * DIM + tid * 8;
    *(float4*)O       = make_float4(o[0], o[1], o[2], o[3]);
    *(float4*)(O + 4) = make_float4(o[4], o[5], o[6], o[7]);
}

extern "C" void kernel_launch(void* const* d_in, const int* in_sizes, int n_in,
                              void* d_out, int out_size)
{
    const float* X  = (const float*)d_in[0];
    const float* Wq = (const float*)d_in[1];
    const float* Wk = (const float*)d_in[2];
    const float* Wv = (const float*)d_in[3];
    float* out = (float*)d_out;

    const int smem_bytes = 4 * STAGE_ELEMS * sizeof(float);   // 73,728 B
    cudaFuncSetAttribute(qkv_gemm,
                         cudaFuncAttributeMaxDynamicSharedMemorySize, smem_bytes);

    dim3 grid_gemm(DIM / 128, BL / 128, 3);   // (8, 128, 3)
    qkv_gemm<<<grid_gemm, 256, smem_bytes>>>(X, Wq, Wk, Wv);
    attn<<<BL, 128>>>(out);
}

// round 8
// speedup vs baseline: 1.2815x; 1.1088x over previous
#include <cuda_runtime.h>
#include <cstdint>

#define BL   (4 * 4096)   // B*L tokens
#define DIM  1024
#define HEADS 16
#define HD    64

#define BM 128
#define BN 256
#define NT (DIM / 32)     // 32 K-tiles of 32 floats
#define NSTAGE 3
#define LDK 36            // padded row: conflict-free ldmatrix row gather
#define A_STAGE (128 * LDK)
#define B_STAGE (256 * LDK)
#define SMEM_BYTES (NSTAGE * (A_STAGE + B_STAGE) * 4)   // 165,888 B

// Static scratch (allowed): projections + tf32-rounded operand copies.
__device__ float g_qkv[3][(size_t)BL * DIM];
__device__ float g_xc[(size_t)BL * DIM];
__device__ float g_wc[3][(size_t)DIM * DIM];

// ---------------- helpers ----------------
__device__ __forceinline__ uint32_t s2u(const void* p) {
    return (uint32_t)__cvta_generic_to_shared(p);
}
__device__ __forceinline__ float f2tf32(float x) {
    uint32_t y; asm("cvt.rna.tf32.f32 %0, %1;" : "=r"(y) : "f"(x));
    return __uint_as_float(y);
}
__device__ __forceinline__ void cp16(uint32_t sdst, const float* g) {
    asm volatile("cp.async.cg.shared.global [%0], [%1], 16;" :: "r"(sdst), "l"(g));
}
// ldmatrix on tf32 data: each 8x4-of-b32 subtile == 8x8-of-b16 tile.
__device__ __forceinline__ void ldsm_x4(uint32_t* r, uint32_t addr) {
    asm volatile("ldmatrix.sync.aligned.m8n8.x4.shared.b16 {%0,%1,%2,%3}, [%4];"
        : "=r"(r[0]), "=r"(r[1]), "=r"(r[2]), "=r"(r[3]) : "r"(addr));
}
__device__ __forceinline__ void mma_tf32(float* d,
    uint32_t a0, uint32_t a1, uint32_t a2, uint32_t a3,
    uint32_t b0, uint32_t b1)
{
    asm volatile(
        "mma.sync.aligned.m16n8k8.row.col.f32.tf32.tf32.f32 "
        "{%0,%1,%2,%3}, {%4,%5,%6,%7}, {%8,%9}, {%0,%1,%2,%3};"
        : "+f"(d[0]), "+f"(d[1]), "+f"(d[2]), "+f"(d[3])
        : "r"(a0), "r"(a1), "r"(a2), "r"(a3), "r"(b0), "r"(b1));
}

// ---------------- pre-pass: cvt.rna tf32 copies ----------------
__global__ __launch_bounds__(256) void conv_tf32(
    const float4* __restrict__ X, const float4* __restrict__ Wq,
    const float4* __restrict__ Wk, const float4* __restrict__ Wv)
{
    const int NX = BL * DIM / 4;
    const int NW = DIM * DIM / 4;
    const int stride = gridDim.x * blockDim.x;
    float4* xc = (float4*)g_xc;
    for (int k = blockIdx.x * blockDim.x + threadIdx.x; k < NX; k += stride) {
        float4 v = X[k];
        v.x = f2tf32(v.x); v.y = f2tf32(v.y); v.z = f2tf32(v.z); v.w = f2tf32(v.w);
        xc[k] = v;
    }
    for (int k = blockIdx.x * blockDim.x + threadIdx.x; k < NW; k += stride) {
        float4 a = Wq[k], b = Wk[k], c = Wv[k];
        a.x = f2tf32(a.x); a.y = f2tf32(a.y); a.z = f2tf32(a.z); a.w = f2tf32(a.w);
        b.x = f2tf32(b.x); b.y = f2tf32(b.y); b.z = f2tf32(b.z); b.w = f2tf32(b.w);
        c.x = f2tf32(c.x); c.y = f2tf32(c.y); c.z = f2tf32(c.z); c.w = f2tf32(c.w);
        ((float4*)g_wc[0])[k] = a;
        ((float4*)g_wc[1])[k] = b;
        ((float4*)g_wc[2])[k] = c;
    }
}

// ---------------- mma.sync tf32 GEMM ----------------
// C[m][n] = sum_k Xc[m][k] * Wc[n][k]. CTA 128x256, 8 warps (2M x 4N),
// warp tile 64x64. 3-stage cp.async pipeline, ldmatrix fragment loads,
// operands pre-rounded to tf32 (no in-loop cvt).
__global__ __launch_bounds__(256, 1) void qkv_gemm()
{
    extern __shared__ float smem[];
    float* As = smem;                       // [NSTAGE][128][LDK]
    float* Bs = smem + NSTAGE * A_STAGE;    // [NSTAGE][256][LDK]

    const int z = blockIdx.z;
    const float* X = g_xc;
    const float* W = g_wc[z];
    float* C = g_qkv[z];

    const int bm = blockIdx.y * BM;
    const int bn = blockIdx.x * BN;

    const int tid  = threadIdx.x;
    const int warp = tid >> 5;
    const int lane = tid & 31;
    const int wm = (warp & 1) * 64;
    const int wn = (warp >> 1) * 64;
    const int g  = lane >> 2;
    const int t  = lane & 3;

    // ldmatrix per-lane row addressing.
    // A x4 subtiles: (rows+0..7,klo)(rows+8..15,klo)(rows+0..7,khi)(rows+8..15,khi)
    const int aRow = (lane & 7) + (lane & 8);
    const int aK   = (lane & 16) >> 2;
    // B x4 subtiles: (cols+0..7,klo)(cols+0..7,khi)(cols+8..15,klo)(cols+8..15,khi)
    const int bCol = (lane & 7) + ((lane & 16) >> 1);
    const int bK   = (lane & 8) >> 1;

    float acc[4][8][4];
    #pragma unroll
    for (int i = 0; i < 4; i++)
        #pragma unroll
        for (int j = 0; j < 8; j++)
            #pragma unroll
            for (int k = 0; k < 4; k++) acc[i][j][k] = 0.f;

    // Cooperative loads: A 1024 16B-chunks (4/thread), B 2048 (8/thread).
    auto load_tile = [&](int s, int kt) {
        const int k0 = kt * 32;
        float* Ad = As + s * A_STAGE;
        float* Bd = Bs + s * B_STAGE;
        #pragma unroll
        for (int i = 0; i < 4; i++) {
            int ch = tid + i * 256;
            int r = ch >> 3, c = ch & 7;
            cp16(s2u(Ad + r * LDK + c * 4), X + (size_t)(bm + r) * DIM + k0 + c * 4);
        }
        #pragma unroll
        for (int i = 0; i < 8; i++) {
            int ch = tid + i * 256;
            int r = ch >> 3, c = ch & 7;
            cp16(s2u(Bd + r * LDK + c * 4), W + (size_t)(bn + r) * DIM + k0 + c * 4);
        }
        asm volatile("cp.async.commit_group;");
    };

    load_tile(0, 0);
    load_tile(1, 1);

    for (int kt = 0; kt < NT; kt++) {
        if (kt < NT - 1) asm volatile("cp.async.wait_group 1;");
        else             asm volatile("cp.async.wait_group 0;");
        __syncthreads();

        const int s = kt % 3;
        const uint32_t aBase = s2u(As + s * A_STAGE) + ((wm + aRow) * LDK + aK) * 4;
        const uint32_t bBase = s2u(Bs + s * B_STAGE) + ((wn + bCol) * LDK + bK) * 4;

        #pragma unroll
        for (int ks = 0; ks < 4; ks++) {
            uint32_t a[4][4], b[4][4];
            #pragma unroll
            for (int mt = 0; mt < 4; mt++)
                ldsm_x4(a[mt], aBase + (mt * 16 * LDK + ks * 8) * 4);
            #pragma unroll
            for (int j = 0; j < 4; j++)
                ldsm_x4(b[j], bBase + (j * 16 * LDK + ks * 8) * 4);
            #pragma unroll
            for (int mt = 0; mt < 4; mt++)
                #pragma unroll
                for (int j = 0; j < 4; j++) {
                    mma_tf32(acc[mt][2 * j],
                             a[mt][0], a[mt][1], a[mt][2], a[mt][3],
                             b[j][0], b[j][1]);
                    mma_tf32(acc[mt][2 * j + 1],
                             a[mt][0], a[mt][1], a[mt][2], a[mt][3],
                             b[j][2], b[j][3]);
                }
        }
        // Stage (kt+2)%3 == (kt-1)%3: all warps finished reading it before
        // the sync at the top of this iteration.
        if (kt + 2 < NT) load_tile((kt + 2) % 3, kt + 2);
    }

    #pragma unroll
    for (int mt = 0; mt < 4; mt++) {
        #pragma unroll
        for (int nt = 0; nt < 8; nt++) {
            int row = bm + wm + mt * 16 + g;
            int col = bn + wn + nt * 8 + t * 2;
            *(float2*)&C[(size_t)row * DIM + col] =
                make_float2(acc[mt][nt][0], acc[mt][nt][1]);
            *(float2*)&C[(size_t)(row + 8) * DIM + col] =
                make_float2(acc[mt][nt][2], acc[mt][nt][3]);
        }
    }
}

// ---------------- fused per-token attention (unchanged) ----------------
__global__ __launch_bounds__(128) void attn(float* __restrict__ out)
{
    const int tok = blockIdx.x;
    const int tid = threadIdx.x;

    __shared__ __align__(16) float sQ[HEADS][68];
    __shared__ __align__(16) float sK[HD][17];
    __shared__ __align__(16) float sV[HEADS][HD];
    __shared__ __align__(16) float sM[HEADS][17];

    const float* Qp = g_qkv[0] + (size_t)tok * DIM;
    const float* Kp = g_qkv[1] + (size_t)tok * DIM;
    const float* Vp = g_qkv[2] + (size_t)tok * DIM;

    #pragma unroll
    for (int i = tid; i < 256; i += 128) {
        int h = i >> 4;
        int d = (i & 15) * 4;
        float4 q = ((const float4*)Qp)[i];
        *(float4*)&sQ[h][d] = q;
        float4 v = ((const float4*)Vp)[i];
        *(float4*)&sV[h][d] = v;
        float4 kf = ((const float4*)Kp)[i];
        sK[d + 0][h] = kf.x; sK[d + 1][h] = kf.y;
        sK[d + 2][h] = kf.z; sK[d + 3][h] = kf.w;
    }
    __syncthreads();

    if (tid < 64) {
        const int d = tid;
        float mx = -1e30f;
        #pragma unroll
        for (int h = 0; h < HEADS; h++) mx = fmaxf(mx, sK[d][h]);
        float e[HEADS], s = 0.f;
        #pragma unroll
        for (int h = 0; h < HEADS; h++) { e[h] = __expf(sK[d][h] - mx); s += e[h]; }
        const float r = 1.f / s;
        #pragma unroll
        for (int h = 0; h < HEADS; h++) sK[d][h] = e[h] * r;
    } else if (tid < 64 + HEADS) {
        const int h = tid - 64;
        float mx = -1e30f;
        for (int d = 0; d < HD; d++) mx = fmaxf(mx, sQ[h][d]);
        float s = 0.f;
        for (int d = 0; d < HD; d++) { float e = __expf(sQ[h][d] - mx); sQ[h][d] = e; s += e; }
        const float r = 1.f / s;
        for (int d = 0; d < HD; d++) sQ[h][d] *= r;
    }
    __syncthreads();

    if (tid < 64) {
        const int i0 = (tid >> 3) * 2;
        const int j0 = (tid & 7) * 2;
        float m00 = 0.f, m01 = 0.f, m10 = 0.f, m11 = 0.f;
        #pragma unroll 8
        for (int d = 0; d < HD; d++) {
            float q0 = sQ[i0][d],     q1 = sQ[i0 + 1][d];
            float k0 = sK[d][j0],     k1 = sK[d][j0 + 1];
            m00 += q0 * k0; m01 += q0 * k1;
            m10 += q1 * k0; m11 += q1 * k1;
        }
        sM[i0][j0]     = m00; sM[i0][j0 + 1]     = m01;
        sM[i0 + 1][j0] = m10; sM[i0 + 1][j0 + 1] = m11;
    }
    __syncthreads();

    const int h  = tid >> 3;
    const int e0 = (tid & 7) * 8;
    float o[8];
    #pragma unroll
    for (int i = 0; i < 8; i++) o[i] = 0.f;
    #pragma unroll
    for (int k = 0; k < HEADS; k++) {
        const float m = sM[h][k];
        const float4 v0 = *(const float4*)&sV[k][e0];
        const float4 v1 = *(const float4*)&sV[k][e0 + 4];
        o[0] += m * v0.x; o[1] += m * v0.y; o[2] += m * v0.z; o[3] += m * v0.w;
        o[4] += m * v1.x; o[5] += m * v1.y; o[6] += m * v1.z; o[7] += m * v1.w;
    }
    float* O = out + (size_t)tok * DIM + tid * 8;
    *(float4*)O       = make_float4(o[0], o[1], o[2], o[3]);
    *(float4*)(O + 4) = make_float4(o[4], o[5], o[6], o[7]);
}

extern "C" void kernel_launch(void* const* d_in, const int* in_sizes, int n_in,
                              void* d_out, int out_size)
{
    const float4* X  = (const float4*)d_in[0];
    const float4* Wq = (const float4*)d_in[1];
    const float4* Wk = (const float4*)d_in[2];
    const float4* Wv = (const float4*)d_in[3];
    float* out = (float*)d_out;

    cudaFuncSetAttribute(qkv_gemm,
                         cudaFuncAttributeMaxDynamicSharedMemorySize, SMEM_BYTES);

    conv_tf32<<<2048, 256>>>(X, Wq, Wk, Wv);

    dim3 grid_gemm(DIM / BN, BL / BM, 3);   // (4, 128, 3)
    qkv_gemm<<<grid_gemm, 256, SMEM_BYTES>>>();

    attn<<<BL, 128>>>(out);
}

// round 10
// speedup vs baseline: 2.0684x; 1.6141x over previous
#include <cuda_runtime.h>
#include <cuda_fp16.h>
#include <cstdint>

#define BL   (4 * 4096)   // B*L tokens
#define DIM  1024
#define HEADS 16
#define HD    64

#define BM 128
#define BN 256
#define KT_ELEMS 64                 // K-tile: 64 halves = 128 B rows
#define NT (DIM / KT_ELEMS)         // 16 K-tiles
#define NSTAGE 3
#define LDK 72                      // padded row (halves): conflict-free ldsm
#define A_STAGE (128 * LDK)         // halves
#define B_STAGE (256 * LDK)
#define SMEM_BYTES (NSTAGE * (A_STAGE + B_STAGE) * 2)   // 165,888 B

// Static scratch (allowed): projections + fp16-rounded operand copies.
__device__ float  g_qkv[3][(size_t)BL * DIM];
__device__ __half g_xh[(size_t)BL * DIM];
__device__ __half g_wh[3][(size_t)DIM * DIM];

// ---------------- helpers ----------------
__device__ __forceinline__ uint32_t s2u(const void* p) {
    return (uint32_t)__cvta_generic_to_shared(p);
}
__device__ __forceinline__ void cp16(uint32_t sdst, const void* g) {
    asm volatile("cp.async.cg.shared.global [%0], [%1], 16;" :: "r"(sdst), "l"(g));
}
__device__ __forceinline__ uint32_t packh2(float lo, float hi) {
    uint32_t r;
    asm("cvt.rn.f16x2.f32 %0, %1, %2;" : "=r"(r) : "f"(hi), "f"(lo));
    return r;
}
__device__ __forceinline__ void ldsm_x4(uint32_t* r, uint32_t addr) {
    asm volatile("ldmatrix.sync.aligned.m8n8.x4.shared.b16 {%0,%1,%2,%3}, [%4];"
        : "=r"(r[0]), "=r"(r[1]), "=r"(r[2]), "=r"(r[3]) : "r"(addr));
}
__device__ __forceinline__ void mma_f16(float* d,
    uint32_t a0, uint32_t a1, uint32_t a2, uint32_t a3,
    uint32_t b0, uint32_t b1)
{
    asm volatile(
        "mma.sync.aligned.m16n8k16.row.col.f32.f16.f16.f32 "
        "{%0,%1,%2,%3}, {%4,%5,%6,%7}, {%8,%9}, {%0,%1,%2,%3};"
        : "+f"(d[0]), "+f"(d[1]), "+f"(d[2]), "+f"(d[3])
        : "r"(a0), "r"(a1), "r"(a2), "r"(a3), "r"(b0), "r"(b1));
}

// ---------------- pre-pass: round operands to fp16 ----------------
__global__ __launch_bounds__(256) void conv_fp16(
    const float4* __restrict__ X, const float4* __restrict__ Wq,
    const float4* __restrict__ Wk, const float4* __restrict__ Wv)
{
    const int NX8 = BL * DIM / 8;
    const int NW8 = DIM * DIM / 8;
    const int stride = gridDim.x * blockDim.x;

    auto pack8 = [](float4 v0, float4 v1) {
        uint4 o;
        o.x = packh2(v0.x, v0.y);
        o.y = packh2(v0.z, v0.w);
        o.z = packh2(v1.x, v1.y);
        o.w = packh2(v1.z, v1.w);
        return o;
    };

    uint4* xh = (uint4*)g_xh;
    for (int k = blockIdx.x * blockDim.x + threadIdx.x; k < NX8; k += stride)
        xh[k] = pack8(X[2 * k], X[2 * k + 1]);
    for (int k = blockIdx.x * blockDim.x + threadIdx.x; k < NW8; k += stride) {
        ((uint4*)g_wh[0])[k] = pack8(Wq[2 * k], Wq[2 * k + 1]);
        ((uint4*)g_wh[1])[k] = pack8(Wk[2 * k], Wk[2 * k + 1]);
        ((uint4*)g_wh[2])[k] = pack8(Wv[2 * k], Wv[2 * k + 1]);
    }
}

// ---------------- fp16 mma.sync GEMM ----------------
// C[m][n] = sum_k Xh[m][k] * Wh[n][k]. CTA 128x256, 8 warps (2M x 4N),
// warp tile 64x64, m16n8k16 f16 with fp32 accumulate.
__global__ __launch_bounds__(256, 1) void qkv_gemm()
{
    extern __shared__ __half smem[];
    __half* As = smem;                      // [NSTAGE][128][LDK]
    __half* Bs = smem + NSTAGE * A_STAGE;   // [NSTAGE][256][LDK]

    const int z = blockIdx.z;
    const __half* X = g_xh;
    const __half* W = g_wh[z];
    float* C = g_qkv[z];

    const int bm = blockIdx.y * BM;
    const int bn = blockIdx.x * BN;

    const int tid  = threadIdx.x;
    const int warp = tid >> 5;
    const int lane = tid & 31;
    const int wm = (warp & 1) * 64;
    const int wn = (warp >> 1) * 64;
    const int g  = lane >> 2;
    const int t  = lane & 3;

    // ldmatrix lane addressing (halves).
    // A x4 tiles: (m0-7,k0)(m8-15,k0)(m0-7,k8)(m8-15,k8)
    const int aRow = (lane & 7) + (lane & 8);
    const int aK   = (lane & 16) >> 1;          // 8 halves = 16 B
    // B x4 tiles: (n0-7,k0)(n0-7,k8)(n8-15,k0)(n8-15,k8)
    const int bCol = (lane & 7) + ((lane & 16) >> 1);
    const int bK   = (lane & 8);                // 8 halves = 16 B

    float acc[4][8][4];
    #pragma unroll
    for (int i = 0; i < 4; i++)
        #pragma unroll
        for (int j = 0; j < 8; j++)
            #pragma unroll
            for (int k = 0; k < 4; k++) acc[i][j][k] = 0.f;

    // Cooperative loads: rows of 8x16B chunks. A: 1024 chunks (4/thr),
    // B: 2048 chunks (8/thr).
    auto load_tile = [&](int s, int kt) {
        const int k0 = kt * KT_ELEMS;
        __half* Ad = As + s * A_STAGE;
        __half* Bd = Bs + s * B_STAGE;
        #pragma unroll
        for (int i = 0; i < 4; i++) {
            int ch = tid + i * 256;
            int r = ch >> 3, c = ch & 7;
            cp16(s2u(Ad + r * LDK + c * 8), X + (size_t)(bm + r) * DIM + k0 + c * 8);
        }
        #pragma unroll
        for (int i = 0; i < 8; i++) {
            int ch = tid + i * 256;
            int r = ch >> 3, c = ch & 7;
            cp16(s2u(Bd + r * LDK + c * 8), W + (size_t)(bn + r) * DIM + k0 + c * 8);
        }
        asm volatile("cp.async.commit_group;");
    };

    load_tile(0, 0);
    load_tile(1, 1);

    for (int kt = 0; kt < NT; kt++) {
        if (kt < NT - 1) asm volatile("cp.async.wait_group 1;");
        else             asm volatile("cp.async.wait_group 0;");
        __syncthreads();

        const int s = kt % 3;
        const uint32_t aBase = s2u(As + s * A_STAGE) + ((wm + aRow) * LDK + aK) * 2;
        const uint32_t bBase = s2u(Bs + s * B_STAGE) + ((wn + bCol) * LDK + bK) * 2;

        #pragma unroll
        for (int ks = 0; ks < 4; ks++) {            // k16 steps
            uint32_t a[4][4], b[4][4];
            #pragma unroll
            for (int mt = 0; mt < 4; mt++)
                ldsm_x4(a[mt], aBase + (mt * 16 * LDK + ks * 16) * 2);
            #pragma unroll
            for (int j = 0; j < 4; j++)
                ldsm_x4(b[j], bBase + (j * 16 * LDK + ks * 16) * 2);
            #pragma unroll
            for (int mt = 0; mt < 4; mt++)
                #pragma unroll
                for (int j = 0; j < 4; j++) {
                    mma_f16(acc[mt][2 * j],
                            a[mt][0], a[mt][1], a[mt][2], a[mt][3],
                            b[j][0], b[j][1]);
                    mma_f16(acc[mt][2 * j + 1],
                            a[mt][0], a[mt][1], a[mt][2], a[mt][3],
                            b[j][2], b[j][3]);
                }
        }
        if (kt + 2 < NT) load_tile((kt + 2) % 3, kt + 2);
    }

    #pragma unroll
    for (int mt = 0; mt < 4; mt++) {
        #pragma unroll
        for (int nt = 0; nt < 8; nt++) {
            int row = bm + wm + mt * 16 + g;
            int col = bn + wn + nt * 8 + t * 2;
            *(float2*)&C[(size_t)row * DIM + col] =
                make_float2(acc[mt][nt][0], acc[mt][nt][1]);
            *(float2*)&C[(size_t)(row + 8) * DIM + col] =
                make_float2(acc[mt][nt][2], acc[mt][nt][3]);
        }
    }
}

// ---------------- fused per-token attention (unchanged) ----------------
__global__ __launch_bounds__(128) void attn(float* __restrict__ out)
{
    const int tok = blockIdx.x;
    const int tid = threadIdx.x;

    __shared__ __align__(16) float sQ[HEADS][68];
    __shared__ __align__(16) float sK[HD][17];
    __shared__ __align__(16) float sV[HEADS][HD];
    __shared__ __align__(16) float sM[HEADS][17];

    const float* Qp = g_qkv[0] + (size_t)tok * DIM;
    const float* Kp = g_qkv[1] + (size_t)tok * DIM;
    const float* Vp = g_qkv[2] + (size_t)tok * DIM;

    #pragma unroll
    for (int i = tid; i < 256; i += 128) {
        int h = i >> 4;
        int d = (i & 15) * 4;
        float4 q = ((const float4*)Qp)[i];
        *(float4*)&sQ[h][d] = q;
        float4 v = ((const float4*)Vp)[i];
        *(float4*)&sV[h][d] = v;
        float4 kf = ((const float4*)Kp)[i];
        sK[d + 0][h] = kf.x; sK[d + 1][h] = kf.y;
        sK[d + 2][h] = kf.z; sK[d + 3][h] = kf.w;
    }
    __syncthreads();

    if (tid < 64) {
        const int d = tid;
        float mx = -1e30f;
        #pragma unroll
        for (int h = 0; h < HEADS; h++) mx = fmaxf(mx, sK[d][h]);
        float e[HEADS], s = 0.f;
        #pragma unroll
        for (int h = 0; h < HEADS; h++) { e[h] = __expf(sK[d][h] - mx); s += e[h]; }
        const float r = 1.f / s;
        #pragma unroll
        for (int h = 0; h < HEADS; h++) sK[d][h] = e[h] * r;
    } else if (tid < 64 + HEADS) {
        const int h = tid - 64;
        float mx = -1e30f;
        for (int d = 0; d < HD; d++) mx = fmaxf(mx, sQ[h][d]);
        float s = 0.f;
        for (int d = 0; d < HD; d++) { float e = __expf(sQ[h][d] - mx); sQ[h][d] = e; s += e; }
        const float r = 1.f / s;
        for (int d = 0; d < HD; d++) sQ[h][d] *= r;
    }
    __syncthreads();

    if (tid < 64) {
        const int i0 = (tid >> 3) * 2;
        const int j0 = (tid & 7) * 2;
        float m00 = 0.f, m01 = 0.f, m10 = 0.f, m11 = 0.f;
        #pragma unroll 8
        for (int d = 0; d < HD; d++) {
            float q0 = sQ[i0][d],     q1 = sQ[i0 + 1][d];
            float k0 = sK[d][j0],     k1 = sK[d][j0 + 1];
            m00 += q0 * k0; m01 += q0 * k1;
            m10 += q1 * k0; m11 += q1 * k1;
        }
        sM[i0][j0]     = m00; sM[i0][j0 + 1]     = m01;
        sM[i0 + 1][j0] = m10; sM[i0 + 1][j0 + 1] = m11;
    }
    __syncthreads();

    const int h  = tid >> 3;
    const int e0 = (tid & 7) * 8;
    float o[8];
    #pragma unroll
    for (int i = 0; i < 8; i++) o[i] = 0.f;
    #pragma unroll
    for (int k = 0; k < HEADS; k++) {
        const float m = sM[h][k];
        const float4 v0 = *(const float4*)&sV[k][e0];
        const float4 v1 = *(const float4*)&sV[k][e0 + 4];
        o[0] += m * v0.x; o[1] += m * v0.y; o[2] += m * v0.z; o[3] += m * v0.w;
        o[4] += m * v1.x; o[5] += m * v1.y; o[6] += m * v1.z; o[7] += m * v1.w;
    }
    float* O = out + (size_t)tok * DIM + tid * 8;
    *(float4*)O       = make_float4(o[0], o[1], o[2], o[3]);
    *(float4*)(O + 4) = make_float4(o[4], o[5], o[6], o[7]);
}

extern "C" void kernel_launch(void* const* d_in, const int* in_sizes, int n_in,
                              void* d_out, int out_size)
{
    const float4* X  = (const float4*)d_in[0];
    const float4* Wq = (const float4*)d_in[1];
    const float4* Wk = (const float4*)d_in[2];
    const float4* Wv = (const float4*)d_in[3];
    float* out = (float*)d_out;

    cudaFuncSetAttribute(qkv_gemm,
                         cudaFuncAttributeMaxDynamicSharedMemorySize, SMEM_BYTES);

    conv_fp16<<<2048, 256>>>(X, Wq, Wk, Wv);

    dim3 grid_gemm(DIM / BN, BL / BM, 3);   // (4, 128, 3)
    qkv_gemm<<<grid_gemm, 256, SMEM_BYTES>>>();

    attn<<<BL, 128>>>(out);
}